// round 16
// baseline (speedup 1.0000x reference)
#include <cuda_runtime.h>

// Reference collapses: softmax(const(-9e15)) == uniform 1/N  =>  adj/a/e dead.
//   out[i,:] = relu( (colsum(h) @ W) / N )  -- one 64-float row broadcast 8192x.
// THREE kernels, no interlock (graph edges are the sync):
//   K1: partial column sums + per-block projection -> g_pproj4 (32 KB)
//       *** all 8 h-loads in ONE asm block: indivisible batch, true MLP=8 ***
//   K2: ONE block reduces the payload -> g_row4
//   K3: 512x256 broadcast, 1 float4 store/thread.

#define N_ROWSC 8192
#define F_INC   512
#define F_OUTC  64
#define GRID    128
#define THREADS 1024
#define TOTAL_F4 (N_ROWSC * F_INC / 4)        // 1,048,576
#define STRIDE   (GRID * THREADS)             // 131,072 float4 (exact cover x8)
#define OUT_F4   (N_ROWSC * F_OUTC / 4)       // 131,072

// Byte strides for immediate-offset loads
#define HSTRB  2097152                        // STRIDE * 16 bytes
#define WSTRB  16384                          // THREADS * 16 bytes

__device__ float4 g_pproj4[GRID * 16];        // 32 KB per-block projections
__device__ float4 g_row4[16];                 // final row (64 floats)

__device__ __forceinline__ void f4add(float4& a, const float4& v) {
    a.x += v.x; a.y += v.y; a.z += v.z; a.w += v.w;
}

// ONE asm statement, 8 LDG.128s, 32 outputs: ptxas cannot interleave consumers,
// so all 8 loads are in flight together and 32 data regs stay live.
#define LDG8_BATCH(p, v, SB)                                                   \
    asm volatile(                                                              \
        "ld.global.nc.v4.f32 {%0,%1,%2,%3},    [%32];\n\t"                     \
        "ld.global.nc.v4.f32 {%4,%5,%6,%7},    [%32+" #SB "];\n\t"             \
        "ld.global.nc.v4.f32 {%8,%9,%10,%11},  [%32+2*" #SB "];\n\t"           \
        "ld.global.nc.v4.f32 {%12,%13,%14,%15},[%32+3*" #SB "];\n\t"           \
        "ld.global.nc.v4.f32 {%16,%17,%18,%19},[%32+4*" #SB "];\n\t"           \
        "ld.global.nc.v4.f32 {%20,%21,%22,%23},[%32+5*" #SB "];\n\t"           \
        "ld.global.nc.v4.f32 {%24,%25,%26,%27},[%32+6*" #SB "];\n\t"           \
        "ld.global.nc.v4.f32 {%28,%29,%30,%31},[%32+7*" #SB "];"               \
        : "=f"(v[0].x), "=f"(v[0].y), "=f"(v[0].z), "=f"(v[0].w),              \
          "=f"(v[1].x), "=f"(v[1].y), "=f"(v[1].z), "=f"(v[1].w),              \
          "=f"(v[2].x), "=f"(v[2].y), "=f"(v[2].z), "=f"(v[2].w),              \
          "=f"(v[3].x), "=f"(v[3].y), "=f"(v[3].z), "=f"(v[3].w),              \
          "=f"(v[4].x), "=f"(v[4].y), "=f"(v[4].z), "=f"(v[4].w),              \
          "=f"(v[5].x), "=f"(v[5].y), "=f"(v[5].z), "=f"(v[5].w),              \
          "=f"(v[6].x), "=f"(v[6].y), "=f"(v[6].z), "=f"(v[6].w),              \
          "=f"(v[7].x), "=f"(v[7].y), "=f"(v[7].z), "=f"(v[7].w)               \
        : "l"(p))

// ---- K1: colsum partials + per-block projection ----
__global__ __launch_bounds__(THREADS)
void k1_colsum_project(const float4* __restrict__ h4,
                       const float4* __restrict__ W4)
{
    __shared__ float4 s4[THREADS];            // 16 KB
    __shared__ float4 s4b[256];               // 4 KB
    __shared__ float  sf[F_INC];              // 2 KB

    const int t = threadIdx.x;
    const int b = blockIdx.x;

    // A: partial column sums; 8 LDG.128s in one indivisible batch.
    {
        const float4* p = h4 + (b * THREADS + t);   // colgroup = t & 127
        float4 v[8];
        LDG8_BATCH(p, v, 2097152);
        float4 acc = v[0];                    // fixed order -> deterministic
        f4add(acc, v[1]); f4add(acc, v[2]); f4add(acc, v[3]);
        f4add(acc, v[4]); f4add(acc, v[5]); f4add(acc, v[6]); f4add(acc, v[7]);
        s4[t] = acc;
    }
    __syncthreads();
    if (t < 128) {                            // 8 partials per column group, fixed order
        float4 a = s4[t];
        #pragma unroll
        for (int j = 1; j < 8; ++j) f4add(a, s4[t + 128 * j]);
        sf[t * 4 + 0] = a.x; sf[t * 4 + 1] = a.y;
        sf[t * 4 + 2] = a.z; sf[t * 4 + 3] = a.w;
    }
    __syncthreads();

    // B: project colsum through W; i = t + j*1024 covers W exactly once.
    // colgroup(i) = i & 15 = t & 15; k(i) = i >> 4.  Batched W loads (L2-warm).
    {
        const float4* wp = W4 + t;
        float4 w[8];
        LDG8_BATCH(wp, w, 16384);
        const int k0 = t >> 4;
        float4 po = make_float4(0.f, 0.f, 0.f, 0.f);
        #pragma unroll
        for (int j = 0; j < 8; ++j) {
            const float s = sf[k0 + j * 64];
            po.x = fmaf(s, w[j].x, po.x); po.y = fmaf(s, w[j].y, po.y);
            po.z = fmaf(s, w[j].z, po.z); po.w = fmaf(s, w[j].w, po.w);
        }
        s4[t] = po;
    }
    __syncthreads();
    if (t < 256) {                            // 1024 -> 256, same colgroup (t&15)
        float4 a = s4[t];
        f4add(a, s4[t + 256]); f4add(a, s4[t + 512]); f4add(a, s4[t + 768]);
        s4b[t] = a;
    }
    __syncthreads();
    if (t < 16) {                             // 256 -> 16, fixed order
        float4 a = s4b[t];
        #pragma unroll
        for (int m = 1; m < 16; ++m) f4add(a, s4b[t + 16 * m]);
        g_pproj4[b * 16 + t] = a;             // colgroup t
    }
}

// ---- K2: ONE block reduces the 2048-float4 payload -> g_row4 ----
__global__ __launch_bounds__(512)
void k2_reduce(void)
{
    __shared__ float4 s4[512];                // 8 KB
    __shared__ float4 s4b[128];               // 2 KB
    const int t = threadIdx.x;

    {
        float4 a  = __ldcg(&g_pproj4[t]);            // colgroup = t & 15
        float4 v1 = __ldcg(&g_pproj4[t +  512]);
        float4 v2 = __ldcg(&g_pproj4[t + 1024]);
        float4 v3 = __ldcg(&g_pproj4[t + 1536]);
        f4add(a, v1); f4add(a, v2); f4add(a, v3);    // fixed order
        s4[t] = a;
    }
    __syncthreads();
    if (t < 128) {                            // 512 -> 128, same colgroup
        float4 a = s4[t];
        f4add(a, s4[t + 128]); f4add(a, s4[t + 256]); f4add(a, s4[t + 384]);
        s4b[t] = a;
    }
    __syncthreads();
    if (t < 16) {                             // 128 -> 16, fixed order
        float4 a = s4b[t];
        #pragma unroll
        for (int m = 1; m < 8; ++m) f4add(a, s4b[t + 16 * m]);
        const float inv = 1.0f / (float)N_ROWSC;
        a.x = fmaxf(a.x * inv, 0.f); a.y = fmaxf(a.y * inv, 0.f);
        a.z = fmaxf(a.z * inv, 0.f); a.w = fmaxf(a.w * inv, 0.f);
        g_row4[t] = a;
    }
}

// ---- K3: broadcast; 512 x 256, one float4 store per thread ----
__global__ __launch_bounds__(256)
void k3_broadcast(float4* __restrict__ out)
{
    __shared__ float4 srow4[16];
    const int t = threadIdx.x;
    if (t < 16) srow4[t] = __ldcg(&g_row4[t]);
    __syncthreads();
    out[blockIdx.x * 256 + t] = srow4[t & 15];   // exact cover of 131072 float4
    (void)OUT_F4;
}

extern "C" void kernel_launch(void* const* d_in, const int* in_sizes, int n_in,
                              void* d_out, int out_size) {
    (void)in_sizes; (void)n_in; (void)out_size;
    const float* h = (const float*)d_in[0];   // (8192, 512) fp32
    // d_in[1] = adj (8192,8192) -- dead code, never read
    const float* W = (const float*)d_in[2];   // (512, 64) fp32
    // d_in[3] = a (128,1)       -- dead code, never read
    float* out = (float*)d_out;               // (8192, 64) fp32

    k1_colsum_project<<<GRID, THREADS>>>((const float4*)h, (const float4*)W);
    k2_reduce<<<1, 512>>>();
    k3_broadcast<<<OUT_F4 / 256, 256>>>((float4*)out);
}